// round 2
// baseline (speedup 1.0000x reference)
#include <cuda_runtime.h>
#include <cuda_bf16.h>
#include <math.h>

#define N_NODES 40000
#define N_EDGES 640000
#define DIM 256
#define NHEAD 8
#define DHEAD 32
#define DFF 1024
#define QK_SCALE 0.0625f   // 256^-0.5

// ---------------- scratch (device globals; no allocations) ----------------
__device__ float g_hln[N_NODES * DIM];        // LN1 output
__device__ float g_qkv[N_NODES * 3 * DIM];    // q|k|v per node (768)
__device__ float g_scores[N_EDGES * NHEAD];   // raw scores, then exp weights
__device__ float g_m[N_NODES * NHEAD];        // segment max
__device__ float g_s[N_NODES * NHEAD];        // segment sum
__device__ float g_x[N_NODES * DIM];          // residual accumulator (x = triplet + agg)
__device__ float g_yln[N_NODES * DIM];        // LN2 output
__device__ float g_hid[N_NODES * DFF];        // FFN hidden

// ---------------- helpers ----------------
__device__ __forceinline__ void atomicMaxF(float* addr, float v) {
    if (v >= 0.f) atomicMax((int*)addr, __float_as_int(v));
    else          atomicMin((unsigned int*)addr, __float_as_uint(v));
}

// ---------------- init: x = triplet, m = -inf, s = 0 ----------------
__global__ void init_kernel(const float* __restrict__ triplet) {
    int idx = blockIdx.x * blockDim.x + threadIdx.x;
    if (idx < N_NODES * DIM) g_x[idx] = triplet[idx];
    if (idx < N_NODES * NHEAD) { g_m[idx] = -INFINITY; g_s[idx] = 0.f; }
}

// ---------------- layernorm: one warp per row ----------------
__global__ void ln_kernel(const float* __restrict__ x, const float* __restrict__ g,
                          const float* __restrict__ b, float* __restrict__ out) {
    int row = blockIdx.x * 8 + threadIdx.y;
    if (row >= N_NODES) return;
    int lane = threadIdx.x;
    const float4* xr = (const float4*)(x + (size_t)row * DIM);
    float4 v0 = xr[lane];
    float4 v1 = xr[lane + 32];
    float sum = v0.x + v0.y + v0.z + v0.w + v1.x + v1.y + v1.z + v1.w;
    float sq  = v0.x*v0.x + v0.y*v0.y + v0.z*v0.z + v0.w*v0.w
              + v1.x*v1.x + v1.y*v1.y + v1.z*v1.z + v1.w*v1.w;
    #pragma unroll
    for (int o = 16; o > 0; o >>= 1) {
        sum += __shfl_xor_sync(0xFFFFFFFFu, sum, o);
        sq  += __shfl_xor_sync(0xFFFFFFFFu, sq,  o);
    }
    float mu = sum * (1.f / DIM);
    float var = sq * (1.f / DIM) - mu * mu;
    float rstd = rsqrtf(var + 1e-5f);
    const float4* gg = (const float4*)g;
    const float4* bb = (const float4*)b;
    float4 g0 = gg[lane], g1 = gg[lane + 32];
    float4 b0 = bb[lane], b1 = bb[lane + 32];
    float4 o0, o1;
    o0.x = (v0.x - mu) * rstd * g0.x + b0.x;
    o0.y = (v0.y - mu) * rstd * g0.y + b0.y;
    o0.z = (v0.z - mu) * rstd * g0.z + b0.z;
    o0.w = (v0.w - mu) * rstd * g0.w + b0.w;
    o1.x = (v1.x - mu) * rstd * g1.x + b1.x;
    o1.y = (v1.y - mu) * rstd * g1.y + b1.y;
    o1.z = (v1.z - mu) * rstd * g1.z + b1.z;
    o1.w = (v1.w - mu) * rstd * g1.w + b1.w;
    float4* orow = (float4*)(out + (size_t)row * DIM);
    orow[lane] = o0;
    orow[lane + 32] = o1;
}

// ---------------- SGEMM: C[M,N] = A[M,K] @ B[K,N] + bias (+addend) (+gelu) --------
// BM=64, BN=128, BK=16, 256 threads, 4x8 per thread. M%64==0, N%128==0, K%16==0.
#define BM 64
#define BN 128
#define BK 16
__global__ __launch_bounds__(256) void sgemm_kernel(
    const float* __restrict__ A, const float* __restrict__ B,
    const float* __restrict__ bias, const float* __restrict__ addend,
    float* __restrict__ C, int M, int N, int K, int act) {
    __shared__ float As[BK][BM];
    __shared__ float Bs[BK][BN];
    int tid = threadIdx.x;
    int tx = tid & 15, ty = tid >> 4;
    int arow = tid >> 2, acol = (tid & 3) << 2;
    int brow = tid >> 4, bcol = (tid & 15) << 3;
    const float* Ab = A + (size_t)(blockIdx.y * BM) * K;
    const float* Bb = B + blockIdx.x * BN;
    float acc[4][8];
    #pragma unroll
    for (int i = 0; i < 4; i++)
        #pragma unroll
        for (int j = 0; j < 8; j++) acc[i][j] = 0.f;

    for (int k0 = 0; k0 < K; k0 += BK) {
        float4 a = *(const float4*)(Ab + (size_t)arow * K + k0 + acol);
        As[acol + 0][arow] = a.x;
        As[acol + 1][arow] = a.y;
        As[acol + 2][arow] = a.z;
        As[acol + 3][arow] = a.w;
        const float* bp = Bb + (size_t)(k0 + brow) * N + bcol;
        *(float4*)&Bs[brow][bcol]     = *(const float4*)bp;
        *(float4*)&Bs[brow][bcol + 4] = *(const float4*)(bp + 4);
        __syncthreads();
        #pragma unroll
        for (int kk = 0; kk < BK; kk++) {
            float ar[4], br[8];
            #pragma unroll
            for (int i = 0; i < 4; i++) ar[i] = As[kk][ty * 4 + i];
            #pragma unroll
            for (int j = 0; j < 8; j++) br[j] = Bs[kk][tx * 8 + j];
            #pragma unroll
            for (int i = 0; i < 4; i++)
                #pragma unroll
                for (int j = 0; j < 8; j++) acc[i][j] += ar[i] * br[j];
        }
        __syncthreads();
    }

    #pragma unroll
    for (int i = 0; i < 4; i++) {
        int row = blockIdx.y * BM + ty * 4 + i;
        int colb = blockIdx.x * BN + tx * 8;
        float v[8];
        #pragma unroll
        for (int j = 0; j < 8; j++) {
            v[j] = acc[i][j] + bias[colb + j];
            if (act == 1) v[j] = 0.5f * v[j] * (1.f + erff(v[j] * 0.70710678118654752f));
        }
        float* cp = C + (size_t)row * N + colb;
        if (addend) {
            const float* ap = addend + (size_t)row * N + colb;
            #pragma unroll
            for (int j = 0; j < 8; j++) v[j] += ap[j];
        }
        float4 s0 = make_float4(v[0], v[1], v[2], v[3]);
        float4 s1 = make_float4(v[4], v[5], v[6], v[7]);
        *(float4*)cp = s0;
        *(float4*)(cp + 4) = s1;
    }
}

// ---------------- edge scores: warp per edge, 8 heads ----------------
__global__ void score_kernel(const int* __restrict__ src, const int* __restrict__ dst) {
    int e = blockIdx.x * 8 + (threadIdx.x >> 5);
    if (e >= N_EDGES) return;
    int lane = threadIdx.x & 31;
    int h = lane >> 2, sub = lane & 3;
    int s = src[e], d = dst[e];
    const float4* qp = (const float4*)(g_qkv + (size_t)s * 768 + h * DHEAD + sub * 8);
    const float4* kp = (const float4*)(g_qkv + (size_t)d * 768 + 256 + h * DHEAD + sub * 8);
    float4 q0 = qp[0], q1 = qp[1];
    float4 k0 = kp[0], k1 = kp[1];
    float p = q0.x*k0.x + q0.y*k0.y + q0.z*k0.z + q0.w*k0.w
            + q1.x*k1.x + q1.y*k1.y + q1.z*k1.z + q1.w*k1.w;
    p += __shfl_xor_sync(0xFFFFFFFFu, p, 1);
    p += __shfl_xor_sync(0xFFFFFFFFu, p, 2);
    if (sub == 0) {
        float sc = p * QK_SCALE;
        g_scores[(size_t)e * NHEAD + h] = sc;
        atomicMaxF(&g_m[d * NHEAD + h], sc);
    }
}

// ---------------- exp + segment sum ----------------
__global__ void expsum_kernel(const int* __restrict__ dst) {
    int idx = blockIdx.x * blockDim.x + threadIdx.x;
    if (idx >= N_EDGES * NHEAD) return;
    int e = idx >> 3, h = idx & 7;
    int d = dst[e];
    float w = expf(g_scores[idx] - g_m[d * NHEAD + h]);
    g_scores[idx] = w;
    atomicAdd(&g_s[d * NHEAD + h], w);
}

// ---------------- aggregate: x[dst] += v[src] * softmax ----------------
__global__ void aggregate_kernel(const int* __restrict__ src, const int* __restrict__ dst) {
    int e = blockIdx.x * 8 + (threadIdx.x >> 5);
    if (e >= N_EDGES) return;
    int lane = threadIdx.x & 31;
    int h = lane >> 2, sub = lane & 3;
    int s = src[e], d = dst[e];
    float w = g_scores[(size_t)e * NHEAD + h];
    float den = g_s[d * NHEAD + h];
    float sa = w / den;
    const float4* vp = (const float4*)(g_qkv + (size_t)s * 768 + 512 + h * DHEAD + sub * 8);
    float4 v0 = vp[0], v1 = vp[1];
    float* out = g_x + (size_t)d * DIM + h * DHEAD + sub * 8;
    atomicAdd(out + 0, v0.x * sa);
    atomicAdd(out + 1, v0.y * sa);
    atomicAdd(out + 2, v0.z * sa);
    atomicAdd(out + 3, v0.w * sa);
    atomicAdd(out + 4, v1.x * sa);
    atomicAdd(out + 5, v1.y * sa);
    atomicAdd(out + 6, v1.z * sa);
    atomicAdd(out + 7, v1.w * sa);
}

// ---------------- launch ----------------
static float* symaddr(const void* sym) {
    void* p = nullptr;
    cudaGetSymbolAddress(&p, sym);
    return (float*)p;
}

extern "C" void kernel_launch(void* const* d_in, const int* in_sizes, int n_in,
                              void* d_out, int out_size) {
    const float* triplet = (const float*)d_in[0];
    const int*   src     = (const int*)d_in[1];
    const int*   dst     = (const int*)d_in[2];
    const float* Wqkv    = (const float*)d_in[3];
    const float* bqkv    = (const float*)d_in[4];
    const float* lnag    = (const float*)d_in[5];
    const float* lnab    = (const float*)d_in[6];
    const float* lnrg    = (const float*)d_in[7];
    const float* lnrb    = (const float*)d_in[8];
    const float* W_in    = (const float*)d_in[9];
    const float* b_in    = (const float*)d_in[10];
    const float* W_out   = (const float*)d_in[11];
    const float* b_out   = (const float*)d_in[12];
    float* out = (float*)d_out;

    float* hln    = symaddr(g_hln);
    float* qkv    = symaddr(g_qkv);
    float* x      = symaddr(g_x);
    float* yln    = symaddr(g_yln);
    float* hid    = symaddr(g_hid);

    dim3 lnblk(32, 8);

    // 1. init
    init_kernel<<<(N_NODES * DIM + 255) / 256, 256>>>(triplet);
    // 2. LN1
    ln_kernel<<<N_NODES / 8, lnblk>>>(triplet, lnag, lnab, hln);
    // 3. QKV gemm: [40000,256]@[256,768]
    sgemm_kernel<<<dim3(768 / BN, N_NODES / BM), 256>>>(hln, Wqkv, bqkv, nullptr, qkv,
                                                        N_NODES, 768, 256, 0);
    // 4. scores + segment max
    score_kernel<<<N_EDGES / 8, 256>>>(src, dst);
    // 5. exp + segment sum
    expsum_kernel<<<(N_EDGES * NHEAD) / 256, 256>>>(dst);
    // 6. aggregate into x
    aggregate_kernel<<<N_EDGES / 8, 256>>>(src, dst);
    // 7. LN2
    ln_kernel<<<N_NODES / 8, lnblk>>>(x, lnrg, lnrb, yln);
    // 8. FFN1 + gelu: [40000,256]@[256,1024]
    sgemm_kernel<<<dim3(DFF / BN, N_NODES / BM), 256>>>(yln, W_in, b_in, nullptr, hid,
                                                        N_NODES, DFF, 256, 1);
    // 9. FFN2 + residual: [40000,1024]@[1024,256] + x -> out
    sgemm_kernel<<<dim3(DIM / BN, N_NODES / BM), 256>>>(hid, W_out, b_out, x, out,
                                                        N_NODES, DIM, DFF, 0);
}

// round 4
// speedup vs baseline: 1.9365x; 1.9365x over previous
#include <cuda_runtime.h>
#include <cuda_bf16.h>
#include <math.h>
#include <stdint.h>

#define N_NODES 40000
#define M_PAD   40064          // 313 * 128
#define N_EDGES 640000
#define DIM 256
#define NHEAD 8
#define DHEAD 32
#define DFF 1024
#define QK_SCALE 0.0625f       // 256^-0.5

// ---------------- scratch (device globals; zero-initialized; no allocations) ----
__device__ __align__(16) float g_qkv[(size_t)M_PAD * 768];     // q|k|v per node
__device__ __align__(16) float g_scores[(size_t)N_EDGES * NHEAD];
__device__ float g_m[N_NODES * NHEAD];
__device__ float g_s[N_NODES * NHEAD];
__device__ __align__(16) float g_x[(size_t)N_NODES * DIM];     // residual accumulator

__device__ __align__(16) __nv_bfloat16 g_hln_h[(size_t)M_PAD * DIM];
__device__ __align__(16) __nv_bfloat16 g_hln_l[(size_t)M_PAD * DIM];
__device__ __align__(16) __nv_bfloat16 g_yln_h[(size_t)M_PAD * DIM];
__device__ __align__(16) __nv_bfloat16 g_yln_l[(size_t)M_PAD * DIM];
__device__ __align__(16) __nv_bfloat16 g_hid_h[(size_t)M_PAD * DFF];
__device__ __align__(16) __nv_bfloat16 g_hid_l[(size_t)M_PAD * DFF];

__device__ __align__(16) __nv_bfloat16 g_wq_h[768 * 256];   // [n][k]
__device__ __align__(16) __nv_bfloat16 g_wq_l[768 * 256];
__device__ __align__(16) __nv_bfloat16 g_wi_h[1024 * 256];
__device__ __align__(16) __nv_bfloat16 g_wi_l[1024 * 256];
__device__ __align__(16) __nv_bfloat16 g_wo_h[256 * 1024];
__device__ __align__(16) __nv_bfloat16 g_wo_l[256 * 1024];

// ---------------- PTX helpers (portable ISA only: sm_80-era) ----------------
__device__ __forceinline__ uint32_t smem_u32(const void* p) {
    return (uint32_t)__cvta_generic_to_shared(p);
}

__device__ __forceinline__ void cp16(uint32_t dst, const void* src) {
    asm volatile("cp.async.cg.shared.global [%0], [%1], 16;" :: "r"(dst), "l"(src));
}

__device__ __forceinline__ void ldsm_x4(uint32_t* r, uint32_t addr) {
    asm volatile("ldmatrix.sync.aligned.m8n8.x4.shared.b16 {%0,%1,%2,%3}, [%4];"
                 : "=r"(r[0]), "=r"(r[1]), "=r"(r[2]), "=r"(r[3]) : "r"(addr));
}

__device__ __forceinline__ void ldsm_x2(uint32_t* r, uint32_t addr) {
    asm volatile("ldmatrix.sync.aligned.m8n8.x2.shared.b16 {%0,%1}, [%2];"
                 : "=r"(r[0]), "=r"(r[1]) : "r"(addr));
}

__device__ __forceinline__ void mma16816(float* c, const uint32_t* a, const uint32_t* b) {
    asm volatile(
        "mma.sync.aligned.m16n8k16.row.col.f32.bf16.bf16.f32 "
        "{%0,%1,%2,%3}, {%4,%5,%6,%7}, {%8,%9}, {%0,%1,%2,%3};"
        : "+f"(c[0]), "+f"(c[1]), "+f"(c[2]), "+f"(c[3])
        : "r"(a[0]), "r"(a[1]), "r"(a[2]), "r"(a[3]), "r"(b[0]), "r"(b[1]));
}

// ---------------- init: x = triplet, m = -inf, s = 0 ----------------
__global__ void init_kernel(const float* __restrict__ triplet) {
    int idx = blockIdx.x * blockDim.x + threadIdx.x;
    if (idx < N_NODES * DIM) g_x[idx] = triplet[idx];
    if (idx < N_NODES * NHEAD) { g_m[idx] = -INFINITY; g_s[idx] = 0.f; }
}

// ---------------- weight prep: transpose + bf16 hi/lo split -----------------
__global__ void wprep_kernel(const float* __restrict__ W, __nv_bfloat16* __restrict__ Bh,
                             __nv_bfloat16* __restrict__ Bl, int K, int Nt) {
    int idx = blockIdx.x * blockDim.x + threadIdx.x;
    if (idx >= K * Nt) return;
    int k = idx / Nt, n = idx - k * Nt;
    float v = W[idx];
    __nv_bfloat16 h = __float2bfloat16(v);
    float lo = v - __bfloat162float(h);
    Bh[(size_t)n * K + k] = h;
    Bl[(size_t)n * K + k] = __float2bfloat16(lo);
}

// ---------------- layernorm with bf16 hi/lo split output --------------------
__device__ __forceinline__ void split_store4(__nv_bfloat16* __restrict__ oh,
                                             __nv_bfloat16* __restrict__ ol,
                                             size_t idx, float4 v) {
    __nv_bfloat16 h0 = __float2bfloat16(v.x), h1 = __float2bfloat16(v.y);
    __nv_bfloat16 h2 = __float2bfloat16(v.z), h3 = __float2bfloat16(v.w);
    __nv_bfloat162 a, b, c, d;
    a.x = h0; a.y = h1; b.x = h2; b.y = h3;
    c.x = __float2bfloat16(v.x - __bfloat162float(h0));
    c.y = __float2bfloat16(v.y - __bfloat162float(h1));
    d.x = __float2bfloat16(v.z - __bfloat162float(h2));
    d.y = __float2bfloat16(v.w - __bfloat162float(h3));
    *(__nv_bfloat162*)(oh + idx)     = a;
    *(__nv_bfloat162*)(oh + idx + 2) = b;
    *(__nv_bfloat162*)(ol + idx)     = c;
    *(__nv_bfloat162*)(ol + idx + 2) = d;
}

__global__ void ln_split_kernel(const float* __restrict__ x, const float* __restrict__ g,
                                const float* __restrict__ b,
                                __nv_bfloat16* __restrict__ oh, __nv_bfloat16* __restrict__ ol) {
    int row = blockIdx.x * 8 + threadIdx.y;
    if (row >= N_NODES) return;
    int lane = threadIdx.x;
    const float4* xr = (const float4*)(x + (size_t)row * DIM);
    float4 v0 = xr[lane];
    float4 v1 = xr[lane + 32];
    float sum = v0.x + v0.y + v0.z + v0.w + v1.x + v1.y + v1.z + v1.w;
    float sq  = v0.x*v0.x + v0.y*v0.y + v0.z*v0.z + v0.w*v0.w
              + v1.x*v1.x + v1.y*v1.y + v1.z*v1.z + v1.w*v1.w;
    #pragma unroll
    for (int o = 16; o > 0; o >>= 1) {
        sum += __shfl_xor_sync(0xFFFFFFFFu, sum, o);
        sq  += __shfl_xor_sync(0xFFFFFFFFu, sq,  o);
    }
    float mu = sum * (1.f / DIM);
    float var = sq * (1.f / DIM) - mu * mu;
    float rstd = rsqrtf(var + 1e-5f);
    const float4* gg = (const float4*)g;
    const float4* bb = (const float4*)b;
    float4 g0 = gg[lane], g1 = gg[lane + 32];
    float4 b0 = bb[lane], b1 = bb[lane + 32];
    float4 o0, o1;
    o0.x = (v0.x - mu) * rstd * g0.x + b0.x;
    o0.y = (v0.y - mu) * rstd * g0.y + b0.y;
    o0.z = (v0.z - mu) * rstd * g0.z + b0.z;
    o0.w = (v0.w - mu) * rstd * g0.w + b0.w;
    o1.x = (v1.x - mu) * rstd * g1.x + b1.x;
    o1.y = (v1.y - mu) * rstd * g1.y + b1.y;
    o1.z = (v1.z - mu) * rstd * g1.z + b1.z;
    o1.w = (v1.w - mu) * rstd * g1.w + b1.w;
    size_t base = (size_t)row * DIM;
    split_store4(oh, ol, base + lane * 4, o0);
    split_store4(oh, ol, base + 128 + lane * 4, o1);
}

// ---------------- mma.sync GEMM: C = A[M,K] @ B[N,K]^T (bf16x3, fp32 acc) ----
// BM=128, BN=64, BK=32, 256 threads, warp tile 32x32 (2x4 m16n8k16 frags).
// Smem stage (30720 B): A_h[128x32]@0, A_l@10240, B_h[64x32]@20480, B_l@25600,
// row stride 80 B (conflict-free ldmatrix). Double-buffered via cp.async.
// mode 0: outf = acc + bias                (QKV)
// mode 1: oh/ol = split(gelu(acc + bias))  (FFN1)
// mode 2: outf = acc + bias + addend       (FFN2 + residual)
#define STAGE_BYTES 30720
#define GEMM_SMEM   (2 * STAGE_BYTES)

__device__ __forceinline__ void gemm_prefetch(
    uint32_t sbase, int s, int tid, int m0, int n0, int kb, int K,
    const __nv_bfloat16* Ah, const __nv_bfloat16* Al,
    const __nv_bfloat16* Bh, const __nv_bfloat16* Bl) {
    uint32_t sp = sbase + s * STAGE_BYTES;
    int row = tid >> 2;
    int cb  = (tid & 3) * 16;            // byte offset within 64B row chunk
    size_t goff = (size_t)kb + (size_t)(tid & 3) * 8;
    // A rows: row and row+64
    {
        uint32_t d = sp + row * 80 + cb;
        cp16(d,         Ah + (size_t)(m0 + row) * K + goff);
        cp16(d + 10240, Al + (size_t)(m0 + row) * K + goff);
        uint32_t d2 = sp + (row + 64) * 80 + cb;
        cp16(d2,         Ah + (size_t)(m0 + row + 64) * K + goff);
        cp16(d2 + 10240, Al + (size_t)(m0 + row + 64) * K + goff);
    }
    // B row
    {
        uint32_t d = sp + 20480 + row * 80 + cb;
        cp16(d,        Bh + (size_t)(n0 + row) * K + goff);
        cp16(d + 5120, Bl + (size_t)(n0 + row) * K + goff);
    }
    asm volatile("cp.async.commit_group;" ::: "memory");
}

__global__ __launch_bounds__(256) void gemm_mma_kernel(
    const __nv_bfloat16* __restrict__ Ah, const __nv_bfloat16* __restrict__ Al,
    const __nv_bfloat16* __restrict__ Bh, const __nv_bfloat16* __restrict__ Bl,
    const float* __restrict__ bias, const float* __restrict__ addend,
    float* __restrict__ outf,
    __nv_bfloat16* __restrict__ oh, __nv_bfloat16* __restrict__ ol,
    int K, int Ntot, int mode) {
    extern __shared__ char smem[];
    const uint32_t sbase = smem_u32(smem);
    const int tid = threadIdx.x;
    const int wid = tid >> 5, lane = tid & 31;
    const int wm = wid & 3, wn = wid >> 2;
    const int m0 = blockIdx.y * 128;
    const int n0 = blockIdx.x * 64;

    float acc[2][4][4];
    #pragma unroll
    for (int i = 0; i < 2; i++)
        #pragma unroll
        for (int j = 0; j < 4; j++)
            #pragma unroll
            for (int q = 0; q < 4; q++) acc[i][j][q] = 0.f;

    const int nk = K >> 5;
    gemm_prefetch(sbase, 0, tid, m0, n0, 0, K, Ah, Al, Bh, Bl);

    const int r16 = lane & 15, ah8 = (lane >> 4) * 8;
    const int br = lane & 7,  bh8 = ((lane >> 3) & 1) * 8;

    for (int kt = 0; kt < nk; kt++) {
        asm volatile("cp.async.wait_group 0;" ::: "memory");
        __syncthreads();
        if (kt + 1 < nk)
            gemm_prefetch(sbase, (kt + 1) & 1, tid, m0, n0, (kt + 1) << 5, K, Ah, Al, Bh, Bl);
        uint32_t sp = sbase + (kt & 1) * STAGE_BYTES;
        #pragma unroll
        for (int ks = 0; ks < 2; ks++) {
            uint32_t ahf[2][4], alf[2][4], bhf[4][2], blf[4][2];
            #pragma unroll
            for (int mi = 0; mi < 2; mi++) {
                uint32_t a = sp + (uint32_t)(wm * 32 + mi * 16 + r16) * 80
                           + (uint32_t)(ks * 16 + ah8) * 2;
                ldsm_x4(ahf[mi], a);
                ldsm_x4(alf[mi], a + 10240);
            }
            #pragma unroll
            for (int ni = 0; ni < 4; ni++) {
                uint32_t a = sp + 20480 + (uint32_t)(wn * 32 + ni * 8 + br) * 80
                           + (uint32_t)(ks * 16 + bh8) * 2;
                ldsm_x2(bhf[ni], a);
                ldsm_x2(blf[ni], a + 5120);
            }
            #pragma unroll
            for (int mi = 0; mi < 2; mi++)
                #pragma unroll
                for (int ni = 0; ni < 4; ni++) {
                    mma16816(acc[mi][ni], ahf[mi], bhf[ni]);
                    mma16816(acc[mi][ni], ahf[mi], blf[ni]);
                    mma16816(acc[mi][ni], alf[mi], bhf[ni]);
                }
        }
        __syncthreads();
    }

    // ---- epilogue ----
    const int rb = m0 + wm * 32 + (lane >> 2);
    const int cb = n0 + wn * 32 + (lane & 3) * 2;
    #pragma unroll
    for (int mi = 0; mi < 2; mi++) {
        #pragma unroll
        for (int half = 0; half < 2; half++) {
            int row = rb + mi * 16 + half * 8;
            if (row >= N_NODES) continue;
            #pragma unroll
            for (int ni = 0; ni < 4; ni++) {
                int col = cb + ni * 8;
                float v0 = acc[mi][ni][half * 2 + 0] + bias[col];
                float v1 = acc[mi][ni][half * 2 + 1] + bias[col + 1];
                if (mode == 0) {
                    *(float2*)(outf + (size_t)row * Ntot + col) = make_float2(v0, v1);
                } else if (mode == 2) {
                    const float* ap = addend + (size_t)row * Ntot + col;
                    *(float2*)(outf + (size_t)row * Ntot + col) =
                        make_float2(v0 + ap[0], v1 + ap[1]);
                } else {
                    v0 = 0.5f * v0 * (1.f + erff(v0 * 0.70710678118654752f));
                    v1 = 0.5f * v1 * (1.f + erff(v1 * 0.70710678118654752f));
                    __nv_bfloat16 h0 = __float2bfloat16(v0), h1 = __float2bfloat16(v1);
                    __nv_bfloat162 hh, ll;
                    hh.x = h0; hh.y = h1;
                    ll.x = __float2bfloat16(v0 - __bfloat162float(h0));
                    ll.y = __float2bfloat16(v1 - __bfloat162float(h1));
                    size_t base = (size_t)row * Ntot + col;
                    *(__nv_bfloat162*)(oh + base) = hh;
                    *(__nv_bfloat162*)(ol + base) = ll;
                }
            }
        }
    }
}

// ---------------- edge scores: warp per edge, 8 heads ----------------
__device__ __forceinline__ void atomicMaxF(float* addr, float v) {
    if (v >= 0.f) atomicMax((int*)addr, __float_as_int(v));
    else          atomicMin((unsigned int*)addr, __float_as_uint(v));
}

__global__ void score_kernel(const int* __restrict__ src, const int* __restrict__ dst) {
    int e = blockIdx.x * 8 + (threadIdx.x >> 5);
    if (e >= N_EDGES) return;
    int lane = threadIdx.x & 31;
    int h = lane >> 2, sub = lane & 3;
    int s = src[e], d = dst[e];
    const float4* qp = (const float4*)(g_qkv + (size_t)s * 768 + h * DHEAD + sub * 8);
    const float4* kp = (const float4*)(g_qkv + (size_t)d * 768 + 256 + h * DHEAD + sub * 8);
    float4 q0 = qp[0], q1 = qp[1];
    float4 k0 = kp[0], k1 = kp[1];
    float p = q0.x*k0.x + q0.y*k0.y + q0.z*k0.z + q0.w*k0.w
            + q1.x*k1.x + q1.y*k1.y + q1.z*k1.z + q1.w*k1.w;
    p += __shfl_xor_sync(0xFFFFFFFFu, p, 1);
    p += __shfl_xor_sync(0xFFFFFFFFu, p, 2);
    if (sub == 0) {
        float sc = p * QK_SCALE;
        g_scores[(size_t)e * NHEAD + h] = sc;
        atomicMaxF(&g_m[d * NHEAD + h], sc);
    }
}

// ---------------- exp + segment sum ----------------
__global__ void expsum_kernel(const int* __restrict__ dst) {
    int idx = blockIdx.x * blockDim.x + threadIdx.x;
    if (idx >= N_EDGES * NHEAD) return;
    int e = idx >> 3, h = idx & 7;
    int d = dst[e];
    float w = expf(g_scores[idx] - g_m[d * NHEAD + h]);
    g_scores[idx] = w;
    atomicAdd(&g_s[d * NHEAD + h], w);
}

// ---------------- aggregate: x[dst] += v[src] * softmax ----------------
__global__ void aggregate_kernel(const int* __restrict__ src, const int* __restrict__ dst) {
    int e = blockIdx.x * 8 + (threadIdx.x >> 5);
    if (e >= N_EDGES) return;
    int lane = threadIdx.x & 31;
    int h = lane >> 2, sub = lane & 3;
    int s = src[e], d = dst[e];
    float w = g_scores[(size_t)e * NHEAD + h];
    float den = g_s[d * NHEAD + h];
    float sa = w / den;
    const float4* vp = (const float4*)(g_qkv + (size_t)s * 768 + 512 + h * DHEAD + sub * 8);
    float4 v0 = vp[0], v1 = vp[1];
    float* out = g_x + (size_t)d * DIM + h * DHEAD + sub * 8;
    atomicAdd(out + 0, v0.x * sa);
    atomicAdd(out + 1, v0.y * sa);
    atomicAdd(out + 2, v0.z * sa);
    atomicAdd(out + 3, v0.w * sa);
    atomicAdd(out + 4, v1.x * sa);
    atomicAdd(out + 5, v1.y * sa);
    atomicAdd(out + 6, v1.z * sa);
    atomicAdd(out + 7, v1.w * sa);
}

// ---------------- launch ----------------
template <typename T>
static T* symaddr(const void* sym) {
    void* p = nullptr;
    cudaGetSymbolAddress(&p, sym);
    return (T*)p;
}

extern "C" void kernel_launch(void* const* d_in, const int* in_sizes, int n_in,
                              void* d_out, int out_size) {
    const float* triplet = (const float*)d_in[0];
    const int*   src     = (const int*)d_in[1];
    const int*   dst     = (const int*)d_in[2];
    const float* Wqkv    = (const float*)d_in[3];
    const float* bqkv    = (const float*)d_in[4];
    const float* lnag    = (const float*)d_in[5];
    const float* lnab    = (const float*)d_in[6];
    const float* lnrg    = (const float*)d_in[7];
    const float* lnrb    = (const float*)d_in[8];
    const float* W_in    = (const float*)d_in[9];
    const float* b_in    = (const float*)d_in[10];
    const float* W_out   = (const float*)d_in[11];
    const float* b_out   = (const float*)d_in[12];
    float* out = (float*)d_out;

    static bool attr_set = false;
    if (!attr_set) {
        cudaFuncSetAttribute(gemm_mma_kernel, cudaFuncAttributeMaxDynamicSharedMemorySize,
                             GEMM_SMEM);
        attr_set = true;
    }

    float* qkv  = symaddr<float>(g_qkv);
    float* x    = symaddr<float>(g_x);
    __nv_bfloat16* hln_h = symaddr<__nv_bfloat16>(g_hln_h);
    __nv_bfloat16* hln_l = symaddr<__nv_bfloat16>(g_hln_l);
    __nv_bfloat16* yln_h = symaddr<__nv_bfloat16>(g_yln_h);
    __nv_bfloat16* yln_l = symaddr<__nv_bfloat16>(g_yln_l);
    __nv_bfloat16* hid_h = symaddr<__nv_bfloat16>(g_hid_h);
    __nv_bfloat16* hid_l = symaddr<__nv_bfloat16>(g_hid_l);
    __nv_bfloat16* wq_h = symaddr<__nv_bfloat16>(g_wq_h);
    __nv_bfloat16* wq_l = symaddr<__nv_bfloat16>(g_wq_l);
    __nv_bfloat16* wi_h = symaddr<__nv_bfloat16>(g_wi_h);
    __nv_bfloat16* wi_l = symaddr<__nv_bfloat16>(g_wi_l);
    __nv_bfloat16* wo_h = symaddr<__nv_bfloat16>(g_wo_h);
    __nv_bfloat16* wo_l = symaddr<__nv_bfloat16>(g_wo_l);

    dim3 lnblk(32, 8);

    // 1. init + weight prep (independent)
    init_kernel<<<(N_NODES * DIM + 255) / 256, 256>>>(triplet);
    wprep_kernel<<<(256 * 768 + 255) / 256, 256>>>(Wqkv, wq_h, wq_l, 256, 768);
    wprep_kernel<<<(256 * 1024 + 255) / 256, 256>>>(W_in, wi_h, wi_l, 256, 1024);
    wprep_kernel<<<(1024 * 256 + 255) / 256, 256>>>(W_out, wo_h, wo_l, 1024, 256);
    // 2. LN1 -> bf16 hi/lo
    ln_split_kernel<<<N_NODES / 8, lnblk>>>(triplet, lnag, lnab, hln_h, hln_l);
    // 3. QKV: [40064,256] @ [256,768] -> fp32 qkv
    gemm_mma_kernel<<<dim3(768 / 64, M_PAD / 128), 256, GEMM_SMEM>>>(
        hln_h, hln_l, wq_h, wq_l, bqkv, nullptr, qkv, nullptr, nullptr, 256, 768, 0);
    // 4-6. edge attention
    score_kernel<<<N_EDGES / 8, 256>>>(src, dst);
    expsum_kernel<<<(N_EDGES * NHEAD) / 256, 256>>>(dst);
    aggregate_kernel<<<N_EDGES / 8, 256>>>(src, dst);
    // 7. LN2 -> bf16 hi/lo
    ln_split_kernel<<<N_NODES / 8, lnblk>>>(x, lnrg, lnrb, yln_h, yln_l);
    // 8. FFN1 + gelu: [40064,256] @ [256,1024] -> bf16 hi/lo hidden
    gemm_mma_kernel<<<dim3(DFF / 64, M_PAD / 128), 256, GEMM_SMEM>>>(
        yln_h, yln_l, wi_h, wi_l, b_in, nullptr, nullptr, hid_h, hid_l, 256, DFF, 1);
    // 9. FFN2 + residual: [40064,1024] @ [1024,256] + x -> out
    gemm_mma_kernel<<<dim3(DIM / 64, M_PAD / 128), 256, GEMM_SMEM>>>(
        hid_h, hid_l, wo_h, wo_l, b_out, x, out, nullptr, nullptr, DFF, DIM, 2);
}

// round 5
// speedup vs baseline: 2.9705x; 1.5340x over previous
#include <cuda_runtime.h>
#include <cuda_bf16.h>
#include <math.h>
#include <stdint.h>

#define N_NODES 40000
#define M_PAD   40064          // 313 * 128
#define N_EDGES 640000
#define DIM 256
#define NHEAD 8
#define DHEAD 32
#define DFF 1024
#define QK_SCALE 0.0625f       // 256^-0.5

// ---------------- scratch (device globals; zero-initialized; no allocations) ----
__device__ __align__(16) float g_qkv[(size_t)M_PAD * 768];     // q|k|v per node
__device__ __align__(16) float g_scores[(size_t)NHEAD * N_EDGES]; // head-major, CSR order
__device__ __align__(16) float g_x[(size_t)N_NODES * DIM];     // x = triplet + agg

__device__ int g_deg[N_NODES];
__device__ int g_off[N_NODES + 1];
__device__ int g_pos[N_NODES];
__device__ int g_eidx[N_EDGES];
__device__ int g_perm[N_EDGES];

__device__ __align__(16) __nv_bfloat16 g_hln_h[(size_t)M_PAD * DIM];
__device__ __align__(16) __nv_bfloat16 g_hln_l[(size_t)M_PAD * DIM];
__device__ __align__(16) __nv_bfloat16 g_yln_h[(size_t)M_PAD * DIM];
__device__ __align__(16) __nv_bfloat16 g_yln_l[(size_t)M_PAD * DIM];
__device__ __align__(16) __nv_bfloat16 g_hid_h[(size_t)M_PAD * DFF];
__device__ __align__(16) __nv_bfloat16 g_hid_l[(size_t)M_PAD * DFF];

__device__ __align__(16) __nv_bfloat16 g_wq_h[768 * 256];   // [n][k]
__device__ __align__(16) __nv_bfloat16 g_wq_l[768 * 256];
__device__ __align__(16) __nv_bfloat16 g_wi_h[1024 * 256];
__device__ __align__(16) __nv_bfloat16 g_wi_l[1024 * 256];
__device__ __align__(16) __nv_bfloat16 g_wo_h[256 * 1024];
__device__ __align__(16) __nv_bfloat16 g_wo_l[256 * 1024];

// ---------------- PTX helpers (portable ISA only: sm_80-era) ----------------
__device__ __forceinline__ uint32_t smem_u32(const void* p) {
    return (uint32_t)__cvta_generic_to_shared(p);
}

__device__ __forceinline__ void cp16(uint32_t dst, const void* src) {
    asm volatile("cp.async.cg.shared.global [%0], [%1], 16;" :: "r"(dst), "l"(src));
}

__device__ __forceinline__ void ldsm_x4(uint32_t* r, uint32_t addr) {
    asm volatile("ldmatrix.sync.aligned.m8n8.x4.shared.b16 {%0,%1,%2,%3}, [%4];"
                 : "=r"(r[0]), "=r"(r[1]), "=r"(r[2]), "=r"(r[3]) : "r"(addr));
}

__device__ __forceinline__ void mma16816(float* c, const uint32_t* a, const uint32_t* b) {
    asm volatile(
        "mma.sync.aligned.m16n8k16.row.col.f32.bf16.bf16.f32 "
        "{%0,%1,%2,%3}, {%4,%5,%6,%7}, {%8,%9}, {%0,%1,%2,%3};"
        : "+f"(c[0]), "+f"(c[1]), "+f"(c[2]), "+f"(c[3])
        : "r"(a[0]), "r"(a[1]), "r"(a[2]), "r"(a[3]), "r"(b[0]), "r"(b[1]));
}

// ---------------- weight prep: transpose + bf16 hi/lo split -----------------
__global__ void wprep_kernel(const float* __restrict__ W, __nv_bfloat16* __restrict__ Bh,
                             __nv_bfloat16* __restrict__ Bl, int K, int Nt) {
    int idx = blockIdx.x * blockDim.x + threadIdx.x;
    if (idx >= K * Nt) return;
    int k = idx / Nt, n = idx - k * Nt;
    float v = W[idx];
    __nv_bfloat16 h = __float2bfloat16(v);
    float lo = v - __bfloat162float(h);
    Bh[(size_t)n * K + k] = h;
    Bl[(size_t)n * K + k] = __float2bfloat16(lo);
}

// ---------------- layernorm with bf16 hi/lo split output --------------------
__device__ __forceinline__ void split_store4(__nv_bfloat16* __restrict__ oh,
                                             __nv_bfloat16* __restrict__ ol,
                                             size_t idx, float4 v) {
    __nv_bfloat16 h0 = __float2bfloat16(v.x), h1 = __float2bfloat16(v.y);
    __nv_bfloat16 h2 = __float2bfloat16(v.z), h3 = __float2bfloat16(v.w);
    __nv_bfloat162 a, b, c, d;
    a.x = h0; a.y = h1; b.x = h2; b.y = h3;
    c.x = __float2bfloat16(v.x - __bfloat162float(h0));
    c.y = __float2bfloat16(v.y - __bfloat162float(h1));
    d.x = __float2bfloat16(v.z - __bfloat162float(h2));
    d.y = __float2bfloat16(v.w - __bfloat162float(h3));
    *(__nv_bfloat162*)(oh + idx)     = a;
    *(__nv_bfloat162*)(oh + idx + 2) = b;
    *(__nv_bfloat162*)(ol + idx)     = c;
    *(__nv_bfloat162*)(ol + idx + 2) = d;
}

__global__ void ln_split_kernel(const float* __restrict__ x, const float* __restrict__ g,
                                const float* __restrict__ b,
                                __nv_bfloat16* __restrict__ oh, __nv_bfloat16* __restrict__ ol) {
    int row = blockIdx.x * 8 + threadIdx.y;
    if (row >= N_NODES) return;
    int lane = threadIdx.x;
    const float4* xr = (const float4*)(x + (size_t)row * DIM);
    float4 v0 = xr[lane];
    float4 v1 = xr[lane + 32];
    float sum = v0.x + v0.y + v0.z + v0.w + v1.x + v1.y + v1.z + v1.w;
    float sq  = v0.x*v0.x + v0.y*v0.y + v0.z*v0.z + v0.w*v0.w
              + v1.x*v1.x + v1.y*v1.y + v1.z*v1.z + v1.w*v1.w;
    #pragma unroll
    for (int o = 16; o > 0; o >>= 1) {
        sum += __shfl_xor_sync(0xFFFFFFFFu, sum, o);
        sq  += __shfl_xor_sync(0xFFFFFFFFu, sq,  o);
    }
    float mu = sum * (1.f / DIM);
    float var = sq * (1.f / DIM) - mu * mu;
    float rstd = rsqrtf(var + 1e-5f);
    const float4* gg = (const float4*)g;
    const float4* bb = (const float4*)b;
    float4 g0 = gg[lane], g1 = gg[lane + 32];
    float4 b0 = bb[lane], b1 = bb[lane + 32];
    float4 o0, o1;
    o0.x = (v0.x - mu) * rstd * g0.x + b0.x;
    o0.y = (v0.y - mu) * rstd * g0.y + b0.y;
    o0.z = (v0.z - mu) * rstd * g0.z + b0.z;
    o0.w = (v0.w - mu) * rstd * g0.w + b0.w;
    o1.x = (v1.x - mu) * rstd * g1.x + b1.x;
    o1.y = (v1.y - mu) * rstd * g1.y + b1.y;
    o1.z = (v1.z - mu) * rstd * g1.z + b1.z;
    o1.w = (v1.w - mu) * rstd * g1.w + b1.w;
    size_t base = (size_t)row * DIM;
    split_store4(oh, ol, base + lane * 4, o0);
    split_store4(oh, ol, base + 128 + lane * 4, o1);
}

// ---------------- CSR build ----------------
__global__ void csr_zero_kernel() {
    int i = blockIdx.x * blockDim.x + threadIdx.x;
    if (i < N_NODES) g_deg[i] = 0;
}

__global__ void csr_count_kernel(const int* __restrict__ dst) {
    int e = blockIdx.x * blockDim.x + threadIdx.x;
    if (e < N_EDGES) atomicAdd(&g_deg[dst[e]], 1);
}

__global__ void csr_scan_kernel() {
    __shared__ int part[1024];
    int t = threadIdx.x;
    const int CH = 40;                 // 1024 * 40 >= N_NODES
    int b = t * CH;
    int sum = 0;
    for (int i = 0; i < CH; i++) {
        int idx = b + i;
        if (idx < N_NODES) sum += g_deg[idx];
    }
    part[t] = sum;
    __syncthreads();
    for (int o = 1; o < 1024; o <<= 1) {
        int v = (t >= o) ? part[t - o] : 0;
        __syncthreads();
        part[t] += v;
        __syncthreads();
    }
    int run = (t > 0) ? part[t - 1] : 0;
    for (int i = 0; i < CH; i++) {
        int idx = b + i;
        if (idx < N_NODES) {
            g_off[idx] = run;
            g_pos[idx] = run;
            run += g_deg[idx];
        }
    }
    if (t == 0) g_off[N_NODES] = N_EDGES;
}

__global__ void csr_fill_kernel(const int* __restrict__ dst) {
    int e = blockIdx.x * blockDim.x + threadIdx.x;
    if (e >= N_EDGES) return;
    int p = atomicAdd(&g_pos[dst[e]], 1);
    g_eidx[p] = e;
    g_perm[e] = p;
}

// ---------------- mma.sync GEMM: C = A[M,K] @ B[N,K]^T (bf16x3, fp32 acc) ----
// BM=128, BN=128, BK=32, 256 threads, warp tile 32x64 (2x8 m16n8k16 frags).
// Smem stage (40960 B): A_h@0, A_l@10240, B_h@20480, B_l@30720; row stride 80 B.
// Double-buffered via cp.async.
// mode 0: outf = acc + bias                (QKV)
// mode 1: oh/ol = split(gelu(acc + bias))  (FFN1)
// mode 2: outf = acc + bias + addend       (FFN2 + residual)
#define STAGE_BYTES 40960
#define GEMM_SMEM   (2 * STAGE_BYTES)

__device__ __forceinline__ void gemm_prefetch(
    uint32_t sbase, int s, int tid, int m0, int n0, int kb, int K,
    const __nv_bfloat16* Ah, const __nv_bfloat16* Al,
    const __nv_bfloat16* Bh, const __nv_bfloat16* Bl) {
    uint32_t sp = sbase + s * STAGE_BYTES;
    int row  = tid >> 1;
    int half = tid & 1;
    uint32_t cb = (uint32_t)half * 32;
    size_t goff = (size_t)kb + (size_t)half * 16;
    uint32_t da = sp + row * 80 + cb;
    const __nv_bfloat16* pa  = Ah + (size_t)(m0 + row) * K + goff;
    const __nv_bfloat16* pal = Al + (size_t)(m0 + row) * K + goff;
    cp16(da, pa);              cp16(da + 16, pa + 8);
    cp16(da + 10240, pal);     cp16(da + 10240 + 16, pal + 8);
    uint32_t db = sp + 20480 + row * 80 + cb;
    const __nv_bfloat16* pb  = Bh + (size_t)(n0 + row) * K + goff;
    const __nv_bfloat16* pbl = Bl + (size_t)(n0 + row) * K + goff;
    cp16(db, pb);              cp16(db + 16, pb + 8);
    cp16(db + 10240, pbl);     cp16(db + 10240 + 16, pbl + 8);
    asm volatile("cp.async.commit_group;" ::: "memory");
}

__global__ __launch_bounds__(256) void gemm_mma_kernel(
    const __nv_bfloat16* __restrict__ Ah, const __nv_bfloat16* __restrict__ Al,
    const __nv_bfloat16* __restrict__ Bh, const __nv_bfloat16* __restrict__ Bl,
    const float* __restrict__ bias, const float* __restrict__ addend,
    float* __restrict__ outf,
    __nv_bfloat16* __restrict__ oh, __nv_bfloat16* __restrict__ ol,
    int K, int Ntot, int mode) {
    extern __shared__ char smem[];
    const uint32_t sbase = smem_u32(smem);
    const int tid = threadIdx.x;
    const int wid = tid >> 5, lane = tid & 31;
    const int wm = wid & 3, wn = wid >> 2;      // wm 0..3, wn 0..1
    const int m0 = blockIdx.y * 128;
    const int n0 = blockIdx.x * 128;

    float acc[2][8][4];
    #pragma unroll
    for (int i = 0; i < 2; i++)
        #pragma unroll
        for (int j = 0; j < 8; j++)
            #pragma unroll
            for (int q = 0; q < 4; q++) acc[i][j][q] = 0.f;

    const int nk = K >> 5;
    gemm_prefetch(sbase, 0, tid, m0, n0, 0, K, Ah, Al, Bh, Bl);

    const int r16 = lane & 15, ah8 = (lane >> 4) * 8;
    const int b8  = lane & 7;
    const int bmi = lane >> 3;                   // 0..3: matrix index within x4
    const int bni = (bmi >> 1) * 8;              // +0 or +8 rows (n pair)
    const int bk8 = (bmi & 1) * 8;               // k half

    for (int kt = 0; kt < nk; kt++) {
        asm volatile("cp.async.wait_group 0;" ::: "memory");
        __syncthreads();
        if (kt + 1 < nk)
            gemm_prefetch(sbase, (kt + 1) & 1, tid, m0, n0, (kt + 1) << 5, K, Ah, Al, Bh, Bl);
        uint32_t sp = sbase + (kt & 1) * STAGE_BYTES;
        #pragma unroll
        for (int ks = 0; ks < 2; ks++) {
            uint32_t ahf[2][4], alf[2][4], bhf[8][2], blf[8][2];
            #pragma unroll
            for (int mi = 0; mi < 2; mi++) {
                uint32_t a = sp + (uint32_t)(wm * 32 + mi * 16 + r16) * 80
                           + (uint32_t)(ks * 16 + ah8) * 2;
                ldsm_x4(ahf[mi], a);
                ldsm_x4(alf[mi], a + 10240);
            }
            #pragma unroll
            for (int pi = 0; pi < 4; pi++) {
                uint32_t a = sp + 20480
                           + (uint32_t)(wn * 64 + pi * 16 + bni + b8) * 80
                           + (uint32_t)(ks * 16 + bk8) * 2;
                uint32_t r[4];
                ldsm_x4(r, a);
                bhf[pi*2][0] = r[0]; bhf[pi*2][1] = r[1];
                bhf[pi*2+1][0] = r[2]; bhf[pi*2+1][1] = r[3];
                ldsm_x4(r, a + 10240);
                blf[pi*2][0] = r[0]; blf[pi*2][1] = r[1];
                blf[pi*2+1][0] = r[2]; blf[pi*2+1][1] = r[3];
            }
            #pragma unroll
            for (int mi = 0; mi < 2; mi++)
                #pragma unroll
                for (int ni = 0; ni < 8; ni++) {
                    mma16816(acc[mi][ni], ahf[mi], bhf[ni]);
                    mma16816(acc[mi][ni], ahf[mi], blf[ni]);
                    mma16816(acc[mi][ni], alf[mi], bhf[ni]);
                }
        }
        __syncthreads();
    }

    // ---- epilogue ----
    const int rb = m0 + wm * 32 + (lane >> 2);
    const int cb = n0 + wn * 64 + (lane & 3) * 2;
    #pragma unroll
    for (int mi = 0; mi < 2; mi++) {
        #pragma unroll
        for (int half = 0; half < 2; half++) {
            int row = rb + mi * 16 + half * 8;
            if (row >= N_NODES) continue;
            #pragma unroll
            for (int ni = 0; ni < 8; ni++) {
                int col = cb + ni * 8;
                float v0 = acc[mi][ni][half * 2 + 0] + bias[col];
                float v1 = acc[mi][ni][half * 2 + 1] + bias[col + 1];
                if (mode == 0) {
                    *(float2*)(outf + (size_t)row * Ntot + col) = make_float2(v0, v1);
                } else if (mode == 2) {
                    const float* ap = addend + (size_t)row * Ntot + col;
                    *(float2*)(outf + (size_t)row * Ntot + col) =
                        make_float2(v0 + ap[0], v1 + ap[1]);
                } else {
                    v0 = 0.5f * v0 * (1.f + erff(v0 * 0.70710678118654752f));
                    v1 = 0.5f * v1 * (1.f + erff(v1 * 0.70710678118654752f));
                    __nv_bfloat16 h0 = __float2bfloat16(v0), h1 = __float2bfloat16(v1);
                    __nv_bfloat162 hh, ll;
                    hh.x = h0; hh.y = h1;
                    ll.x = __float2bfloat16(v0 - __bfloat162float(h0));
                    ll.y = __float2bfloat16(v1 - __bfloat162float(h1));
                    size_t base = (size_t)row * Ntot + col;
                    *(__nv_bfloat162*)(oh + base) = hh;
                    *(__nv_bfloat162*)(ol + base) = ll;
                }
            }
        }
    }
}

// ---------------- edge scores: warp per edge, 8 heads; CSR-permuted output --
__global__ void score_kernel(const int* __restrict__ src, const int* __restrict__ dst) {
    int e = blockIdx.x * 8 + (threadIdx.x >> 5);
    if (e >= N_EDGES) return;
    int lane = threadIdx.x & 31;
    int h = lane >> 2, sub = lane & 3;
    int s = src[e], d = dst[e];
    const float4* qp = (const float4*)(g_qkv + (size_t)s * 768 + h * DHEAD + sub * 8);
    const float4* kp = (const float4*)(g_qkv + (size_t)d * 768 + 256 + h * DHEAD + sub * 8);
    float4 q0 = qp[0], q1 = qp[1];
    float4 k0 = kp[0], k1 = kp[1];
    float p = q0.x*k0.x + q0.y*k0.y + q0.z*k0.z + q0.w*k0.w
            + q1.x*k1.x + q1.y*k1.y + q1.z*k1.z + q1.w*k1.w;
    p += __shfl_xor_sync(0xFFFFFFFFu, p, 1);
    p += __shfl_xor_sync(0xFFFFFFFFu, p, 2);
    if (sub == 0) {
        int pos = g_perm[e];
        g_scores[(size_t)h * N_EDGES + pos] = p * QK_SCALE;
    }
}

// ---------------- fused softmax + aggregate (gather, no atomics) -------------
// block per node, warp per head. x[node] = triplet[node] + sum_e sa_e * v[src_e]
__global__ __launch_bounds__(256) void aggregate_csr_kernel(
    const int* __restrict__ src, const float* __restrict__ triplet) {
    __shared__ int s_src[128];
    int node = blockIdx.x;
    int lane = threadIdx.x & 31;
    int h = threadIdx.x >> 5;
    int beg = g_off[node];
    int deg = g_off[node + 1] - beg;

    const float* sc_base = g_scores + (size_t)h * N_EDGES + beg;

    float m = -INFINITY;
    for (int i = lane; i < deg; i += 32) m = fmaxf(m, sc_base[i]);
    #pragma unroll
    for (int o = 16; o > 0; o >>= 1) m = fmaxf(m, __shfl_xor_sync(0xFFFFFFFFu, m, o));

    float acc = 0.f, ssum = 0.f;
    for (int base = 0; base < deg; base += 128) {
        int cnt = min(128, deg - base);
        __syncthreads();
        for (int i = threadIdx.x; i < cnt; i += 256)
            s_src[i] = src[g_eidx[beg + base + i]];
        __syncthreads();
        for (int c0 = 0; c0 < cnt; c0 += 32) {
            int i = c0 + lane;
            float w = (i < cnt) ? expf(sc_base[base + i] - m) : 0.f;
            ssum += w;
            int cc = min(32, cnt - c0);
            for (int j = 0; j < cc; j++) {
                float wj = __shfl_sync(0xFFFFFFFFu, w, j);
                int sj = s_src[c0 + j];
                acc += g_qkv[(size_t)sj * 768 + 512 + h * 32 + lane] * wj;
            }
        }
    }
    #pragma unroll
    for (int o = 16; o > 0; o >>= 1) ssum += __shfl_xor_sync(0xFFFFFFFFu, ssum, o);
    float res = (ssum > 0.f) ? acc / ssum : 0.f;
    size_t idx = (size_t)node * DIM + h * 32 + lane;
    g_x[idx] = triplet[idx] + res;
}

// ---------------- launch ----------------
template <typename T>
static T* symaddr(const void* sym) {
    void* p = nullptr;
    cudaGetSymbolAddress(&p, sym);
    return (T*)p;
}

extern "C" void kernel_launch(void* const* d_in, const int* in_sizes, int n_in,
                              void* d_out, int out_size) {
    const float* triplet = (const float*)d_in[0];
    const int*   src     = (const int*)d_in[1];
    const int*   dst     = (const int*)d_in[2];
    const float* Wqkv    = (const float*)d_in[3];
    const float* bqkv    = (const float*)d_in[4];
    const float* lnag    = (const float*)d_in[5];
    const float* lnab    = (const float*)d_in[6];
    const float* lnrg    = (const float*)d_in[7];
    const float* lnrb    = (const float*)d_in[8];
    const float* W_in    = (const float*)d_in[9];
    const float* b_in    = (const float*)d_in[10];
    const float* W_out   = (const float*)d_in[11];
    const float* b_out   = (const float*)d_in[12];
    float* out = (float*)d_out;

    static bool attr_set = false;
    if (!attr_set) {
        cudaFuncSetAttribute(gemm_mma_kernel, cudaFuncAttributeMaxDynamicSharedMemorySize,
                             GEMM_SMEM);
        attr_set = true;
    }

    float* qkv = symaddr<float>(g_qkv);
    float* x   = symaddr<float>(g_x);
    __nv_bfloat16* hln_h = symaddr<__nv_bfloat16>(g_hln_h);
    __nv_bfloat16* hln_l = symaddr<__nv_bfloat16>(g_hln_l);
    __nv_bfloat16* yln_h = symaddr<__nv_bfloat16>(g_yln_h);
    __nv_bfloat16* yln_l = symaddr<__nv_bfloat16>(g_yln_l);
    __nv_bfloat16* hid_h = symaddr<__nv_bfloat16>(g_hid_h);
    __nv_bfloat16* hid_l = symaddr<__nv_bfloat16>(g_hid_l);
    __nv_bfloat16* wq_h = symaddr<__nv_bfloat16>(g_wq_h);
    __nv_bfloat16* wq_l = symaddr<__nv_bfloat16>(g_wq_l);
    __nv_bfloat16* wi_h = symaddr<__nv_bfloat16>(g_wi_h);
    __nv_bfloat16* wi_l = symaddr<__nv_bfloat16>(g_wi_l);
    __nv_bfloat16* wo_h = symaddr<__nv_bfloat16>(g_wo_h);
    __nv_bfloat16* wo_l = symaddr<__nv_bfloat16>(g_wo_l);

    dim3 lnblk(32, 8);

    // weight prep + LN1 + CSR build (all independent of each other)
    wprep_kernel<<<(256 * 768 + 255) / 256, 256>>>(Wqkv, wq_h, wq_l, 256, 768);
    wprep_kernel<<<(256 * 1024 + 255) / 256, 256>>>(W_in, wi_h, wi_l, 256, 1024);
    wprep_kernel<<<(1024 * 256 + 255) / 256, 256>>>(W_out, wo_h, wo_l, 1024, 256);
    ln_split_kernel<<<N_NODES / 8, lnblk>>>(triplet, lnag, lnab, hln_h, hln_l);
    csr_zero_kernel<<<(N_NODES + 255) / 256, 256>>>();
    csr_count_kernel<<<(N_EDGES + 255) / 256, 256>>>(dst);
    csr_scan_kernel<<<1, 1024>>>();
    csr_fill_kernel<<<(N_EDGES + 255) / 256, 256>>>(dst);
    // QKV: [40064,256] @ [256,768]
    gemm_mma_kernel<<<dim3(768 / 128, M_PAD / 128), 256, GEMM_SMEM>>>(
        hln_h, hln_l, wq_h, wq_l, bqkv, nullptr, qkv, nullptr, nullptr, 256, 768, 0);
    // attention
    score_kernel<<<N_EDGES / 8, 256>>>(src, dst);
    aggregate_csr_kernel<<<N_NODES, 256>>>(src, triplet);
    // LN2
    ln_split_kernel<<<N_NODES / 8, lnblk>>>(x, lnrg, lnrb, yln_h, yln_l);
    // FFN1 + gelu: [40064,256] @ [256,1024]
    gemm_mma_kernel<<<dim3(DFF / 128, M_PAD / 128), 256, GEMM_SMEM>>>(
        yln_h, yln_l, wi_h, wi_l, b_in, nullptr, nullptr, hid_h, hid_l, 256, DFF, 1);
    // FFN2 + residual: [40064,1024] @ [1024,256] + x -> out
    gemm_mma_kernel<<<dim3(DIM / 128, M_PAD / 128), 256, GEMM_SMEM>>>(
        hid_h, hid_l, wo_h, wo_l, b_out, x, out, nullptr, nullptr, DFF, DIM, 2);
}